// round 14
// baseline (speedup 1.0000x reference)
#include <cuda_runtime.h>
#include <cuda_bf16.h>
#include <math.h>

#define BATCH 8
#define LSEQ 1024
#define DIMC 256
#define NHEADS 8
#define DHEAD 32
#define ECH 64
#define PDIM 1024
#define NPATCH 8192   // BATCH*LSEQ
#define BHDIM 64      // BATCH*NHEADS

// ---------------- scratch (device globals; no allocations allowed) ----------
__device__ float g_conv[NPATCH * ECH * 64];   // 128 MB
__device__ float g_part[NPATCH * 128];
__device__ float g_stats[ECH * 2];
__device__ float g_x[NPATCH * DIMC];
__device__ float g_xn[NPATCH * DIMC];
__device__ float g_m[NPATCH * DIMC];
__device__ float g_q[BHDIM * LSEQ * DHEAD];
__device__ float g_kt[BHDIM * DHEAD * LSEQ];

// bf16 hi/lo pre-split operands
__device__ __nv_bfloat16 g_embin_h[NPATCH * PDIM], g_embin_l[NPATCH * PDIM];
__device__ __nv_bfloat16 g_embw_h[PDIM * DIMC],   g_embw_l[PDIM * DIMC];
__device__ __nv_bfloat16 g_adj_h[LSEQ * LSEQ],    g_adj_l[LSEQ * LSEQ];
__device__ __nv_bfloat16 g_xn_h[NPATCH * DIMC],   g_xn_l[NPATCH * DIMC];
__device__ __nv_bfloat16 g_v_h[NPATCH * DIMC],    g_v_l[NPATCH * DIMC];
__device__ __nv_bfloat16 g_pw_h[4 * DIMC * DIMC], g_pw_l[4 * DIMC * DIMC];

__device__ __forceinline__ float gelu_f(float x) {
    return 0.5f * x * (1.0f + erff(x * 0.70710678118654752440f));
}

__device__ __forceinline__ void split_bf(float v, __nv_bfloat16& h, __nv_bfloat16& l) {
    h = __float2bfloat16(v);
    l = __float2bfloat16(v - __bfloat162float(h));
}

// ---------------- one-time fp32 -> bf16 hi/lo split -------------------------
__global__ __launch_bounds__(256) void split_kernel(
    const float* __restrict__ in, __nv_bfloat16* __restrict__ hi,
    __nv_bfloat16* __restrict__ lo, int n)
{
    int i = blockIdx.x * 256 + threadIdx.x;
    if (i < n) {
        __nv_bfloat16 h, l;
        split_bf(in[i], h, l);
        hi[i] = h; lo[i] = l;
    }
}

// ---------------- conv 3x3 s2 p1, register-tiled + per-patch BN partials ----
// thread: oc = t>>2, quadrant (qy,qx) of the 8x8 output; 27 weights in regs;
// padded 18x20 smem input rows loaded as float4.
__global__ __launch_bounds__(256) void conv_kernel(
    const float* __restrict__ img, const float* __restrict__ w,
    const float* __restrict__ bias, float* __restrict__ out,
    float* __restrict__ part)
{
    int patch = blockIdx.x;
    int b  = patch >> 10;
    int gi = (patch >> 5) & 31;
    int gj = patch & 31;
    __shared__ float s_in[3][18][20];    // zero-padded border, 4320 B
    __shared__ float s_w[ECH * 27];
    __shared__ float s_vals[ECH * 64];   // 16 KB
    int t = threadIdx.x;
    for (int i = t; i < 3 * 18 * 20; i += 256) ((float*)s_in)[i] = 0.0f;
    for (int i = t; i < ECH * 27; i += 256) s_w[i] = w[i];
    __syncthreads();
    for (int i = t; i < 3 * 256; i += 256) {
        int c = i >> 8; int pi = (i >> 4) & 15; int pj = i & 15;
        s_in[c][pi + 1][pj + 1] =
            img[(((long)b * 3 + c) * 512 + gi * 16 + pi) * 512 + gj * 16 + pj];
    }
    __syncthreads();

    int oc = t >> 2, quad = t & 3;
    int qy = quad >> 1, qx = quad & 1;
    float wreg[27];
#pragma unroll
    for (int i = 0; i < 27; i++) wreg[i] = s_w[oc * 27 + i];
    float bv = bias[oc];
    float acc[4][4];
#pragma unroll
    for (int i = 0; i < 4; i++)
#pragma unroll
    for (int j = 0; j < 4; j++) acc[i][j] = bv;

#pragma unroll
    for (int c = 0; c < 3; c++) {
#pragma unroll
        for (int oy = 0; oy < 4; oy++) {
            int oyy = qy * 4 + oy;
            float rr[3][9];
#pragma unroll
            for (int ky = 0; ky < 3; ky++) {
                const float* rp = &s_in[c][2 * oyy + ky][8 * qx];
                float4 v0 = *(const float4*)rp;
                float4 v1 = *(const float4*)(rp + 4);
                rr[ky][0] = v0.x; rr[ky][1] = v0.y; rr[ky][2] = v0.z; rr[ky][3] = v0.w;
                rr[ky][4] = v1.x; rr[ky][5] = v1.y; rr[ky][6] = v1.z; rr[ky][7] = v1.w;
                rr[ky][8] = rp[8];
            }
            const float* wc = &wreg[c * 9];
#pragma unroll
            for (int ox = 0; ox < 4; ox++) {
                float a = acc[oy][ox];
#pragma unroll
                for (int ky = 0; ky < 3; ky++) {
                    a += rr[ky][2 * ox + 0] * wc[ky * 3 + 0];
                    a += rr[ky][2 * ox + 1] * wc[ky * 3 + 1];
                    a += rr[ky][2 * ox + 2] * wc[ky * 3 + 2];
                }
                acc[oy][ox] = a;
            }
        }
    }
    // write outputs + stage for partial reduce
#pragma unroll
    for (int oy = 0; oy < 4; oy++) {
        int oyy = qy * 4 + oy;
#pragma unroll
        for (int ox = 0; ox < 4; ox++) {
            int pos = oyy * 8 + qx * 4 + ox;
            out[(long)patch * 4096 + oc * 64 + pos] = acc[oy][ox];
            s_vals[oc * 64 + pos] = acc[oy][ox];
        }
    }
    __syncthreads();
    if (t < ECH) {
        float s = 0.0f, ss = 0.0f;
        const float* vp = &s_vals[t * 64];
#pragma unroll
        for (int i = 0; i < 64; i++) { float v = vp[i]; s += v; ss += v * v; }
        part[(long)patch * 128 + t]      = s;
        part[(long)patch * 128 + 64 + t] = ss;
    }
}

// ---------------- BN statistics from per-patch partials ---------------------
__global__ __launch_bounds__(256) void bn_stats_kernel(
    const float* __restrict__ part, float* __restrict__ stats)
{
    int c = blockIdx.x, t = threadIdx.x;
    double s = 0.0, ss = 0.0;
    for (int p = t; p < NPATCH; p += 256) {
        s  += (double)part[(long)p * 128 + c];
        ss += (double)part[(long)p * 128 + 64 + c];
    }
    __shared__ double sh1[256], sh2[256];
    sh1[t] = s; sh2[t] = ss;
    __syncthreads();
    for (int o = 128; o > 0; o >>= 1) {
        if (t < o) { sh1[t] += sh1[t + o]; sh2[t] += sh2[t + o]; }
        __syncthreads();
    }
    if (t == 0) {
        double mean = sh1[0] / 524288.0;
        double var  = sh2[0] / 524288.0 - mean * mean;
        stats[2 * c]     = (float)mean;
        stats[2 * c + 1] = rsqrtf((float)var + 1e-5f);
    }
}

// ---------------- BN + GELU + maxpool + flatten -> bf16 hi/lo ---------------
__global__ __launch_bounds__(256) void bn_gelu_pool_kernel(
    const float* __restrict__ conv, const float* __restrict__ stats,
    const float* __restrict__ bn_g, const float* __restrict__ bn_b,
    __nv_bfloat16* __restrict__ oh, __nv_bfloat16* __restrict__ ol)
{
    int patch = blockIdx.x;
    __shared__ float s[ECH * 64];
    int t = threadIdx.x;
    for (int i = t; i < ECH * 64; i += 256) {
        int c = i >> 6;
        float mean = stats[2 * c], rstd = stats[2 * c + 1];
        float x = (conv[(long)patch * 4096 + i] - mean) * rstd * bn_g[c] + bn_b[c];
        s[i] = gelu_f(x);
    }
    __syncthreads();
    for (int i = t; i < ECH * 16; i += 256) {
        int c = i >> 4; int pos = i & 15;
        int oy = pos >> 2, ox = pos & 3;
        float m = -INFINITY;
        for (int wy = 2 * oy - 1; wy <= 2 * oy + 1; wy++) {
            if (wy < 0 || wy > 7) continue;
            for (int wx = 2 * ox - 1; wx <= 2 * ox + 1; wx++) {
                if (wx < 0 || wx > 7) continue;
                m = fmaxf(m, s[c * 64 + wy * 8 + wx]);
            }
        }
        __nv_bfloat16 h, l;
        split_bf(m, h, l);
        oh[(long)patch * PDIM + i] = h;
        ol[(long)patch * PDIM + i] = l;
    }
}

// =====================================================================
// Pre-split 3xBF16 tensor-core GEMM: C = A@B (+bias)(+res), fp32 out.
// =====================================================================
__device__ __forceinline__ void mma_bf16(
    float& c0, float& c1, float& c2, float& c3,
    unsigned a0, unsigned a1, unsigned a2, unsigned a3,
    unsigned b0, unsigned b1)
{
    asm volatile(
        "mma.sync.aligned.m16n8k16.row.col.f32.bf16.bf16.f32 "
        "{%0,%1,%2,%3}, {%4,%5,%6,%7}, {%8,%9}, {%0,%1,%2,%3};"
        : "+f"(c0), "+f"(c1), "+f"(c2), "+f"(c3)
        : "r"(a0), "r"(a1), "r"(a2), "r"(a3), "r"(b0), "r"(b1));
}

__global__ __launch_bounds__(256, 2) void gemm_bf(
    const __nv_bfloat16* __restrict__ Ahg, const __nv_bfloat16* __restrict__ Alg,
    const __nv_bfloat16* __restrict__ Bhg, const __nv_bfloat16* __restrict__ Blg,
    const float* __restrict__ bias, const float* __restrict__ res,
    float* __restrict__ C, int K,
    long zB, long zRes, long zC,
    int lda, int ldb, int ldres, int ldc)
{
    long bz = blockIdx.z;
    Bhg += zB * bz; Blg += zB * bz; C += zC * bz;
    if (res) res += zRes * bz;
    int m0 = blockIdx.y * 128, n0 = blockIdx.x * 64;

    __shared__ __nv_bfloat16 Ash[128 * 40], Asl[128 * 40];
    __shared__ __nv_bfloat16 Bsh[64 * 40],  Bsl[64 * 40];

    int t = threadIdx.x, lane = t & 31, w = t >> 5;
    int wm = w & 3, wn = w >> 2;
    int gid = lane >> 2, tig = lane & 3;

    float acc[2][4][4] = {};

    int a_row[2], a_kq[2];
#pragma unroll
    for (int p = 0; p < 2; p++) {
        int i = t + 256 * p;
        a_row[p] = i >> 2;
        a_kq[p]  = (i & 3) * 8;
    }
    int b_kr = t >> 3, b_nq = (t & 7) * 8;

    uint4 arh[2], arl[2], brh, brl;
#pragma unroll
    for (int p = 0; p < 2; p++) {
        long off = (long)(m0 + a_row[p]) * lda + a_kq[p];
        arh[p] = *(const uint4*)(Ahg + off);
        arl[p] = *(const uint4*)(Alg + off);
    }
    {
        long off = (long)b_kr * ldb + n0 + b_nq;
        brh = *(const uint4*)(Bhg + off);
        brl = *(const uint4*)(Blg + off);
    }

    int nch = K >> 5;
    for (int c = 0; c < nch; c++) {
#pragma unroll
        for (int p = 0; p < 2; p++) {
            *(uint4*)&Ash[a_row[p] * 40 + a_kq[p]] = arh[p];
            *(uint4*)&Asl[a_row[p] * 40 + a_kq[p]] = arl[p];
        }
        {
            const __nv_bfloat16* h8 = (const __nv_bfloat16*)&brh;
            const __nv_bfloat16* l8 = (const __nv_bfloat16*)&brl;
#pragma unroll
            for (int j = 0; j < 8; j++) {
                Bsh[(b_nq + j) * 40 + b_kr] = h8[j];
                Bsl[(b_nq + j) * 40 + b_kr] = l8[j];
            }
        }
        __syncthreads();
        if (c + 1 < nch) {
            int kc = (c + 1) << 5;
#pragma unroll
            for (int p = 0; p < 2; p++) {
                long off = (long)(m0 + a_row[p]) * lda + kc + a_kq[p];
                arh[p] = *(const uint4*)(Ahg + off);
                arl[p] = *(const uint4*)(Alg + off);
            }
            long off = (long)(kc + b_kr) * ldb + n0 + b_nq;
            brh = *(const uint4*)(Bhg + off);
            brl = *(const uint4*)(Blg + off);
        }
#pragma unroll
        for (int ks = 0; ks < 2; ks++) {
            int k0 = ks * 16;
            unsigned bh[4][2], bl[4][2];
#pragma unroll
            for (int nt = 0; nt < 4; nt++) {
                int bb = (wn * 32 + nt * 8 + gid) * 40 + k0 + tig * 2;
                bh[nt][0] = *(const unsigned*)&Bsh[bb];
                bh[nt][1] = *(const unsigned*)&Bsh[bb + 8];
                bl[nt][0] = *(const unsigned*)&Bsl[bb];
                bl[nt][1] = *(const unsigned*)&Bsl[bb + 8];
            }
#pragma unroll
            for (int mt = 0; mt < 2; mt++) {
                int ab = (wm * 32 + mt * 16 + gid) * 40 + k0 + tig * 2;
                unsigned ah0 = *(const unsigned*)&Ash[ab];
                unsigned ah1 = *(const unsigned*)&Ash[ab + 8 * 40];
                unsigned ah2 = *(const unsigned*)&Ash[ab + 8];
                unsigned ah3 = *(const unsigned*)&Ash[ab + 8 * 40 + 8];
                unsigned al0 = *(const unsigned*)&Asl[ab];
                unsigned al1 = *(const unsigned*)&Asl[ab + 8 * 40];
                unsigned al2 = *(const unsigned*)&Asl[ab + 8];
                unsigned al3 = *(const unsigned*)&Asl[ab + 8 * 40 + 8];
#pragma unroll
                for (int nt = 0; nt < 4; nt++) {
                    float* cc = acc[mt][nt];
                    mma_bf16(cc[0], cc[1], cc[2], cc[3],
                             ah0, ah1, ah2, ah3, bh[nt][0], bh[nt][1]);
                    mma_bf16(cc[0], cc[1], cc[2], cc[3],
                             ah0, ah1, ah2, ah3, bl[nt][0], bl[nt][1]);
                    mma_bf16(cc[0], cc[1], cc[2], cc[3],
                             al0, al1, al2, al3, bh[nt][0], bh[nt][1]);
                }
            }
        }
        __syncthreads();
    }
#pragma unroll
    for (int mt = 0; mt < 2; mt++) {
        int r = m0 + wm * 32 + mt * 16 + gid;
#pragma unroll
        for (int nt = 0; nt < 4; nt++) {
            int n = n0 + wn * 32 + nt * 8 + tig * 2;
            float bx = 0.f, by = 0.f;
            if (bias) { float2 bv = *(const float2*)(bias + n); bx = bv.x; by = bv.y; }
            float* cc = acc[mt][nt];
            float2 v0 = make_float2(cc[0] + bx, cc[1] + by);
            float2 v1 = make_float2(cc[2] + bx, cc[3] + by);
            if (res) {
                float2 r0 = *(const float2*)(res + (long)r * ldres + n);
                float2 r1 = *(const float2*)(res + (long)(r + 8) * ldres + n);
                v0.x += r0.x; v0.y += r0.y; v1.x += r1.x; v1.y += r1.y;
            }
            *(float2*)(C + (long)r * ldc + n) = v0;
            *(float2*)(C + (long)(r + 8) * ldc + n) = v1;
        }
    }
}

// ---------------- layernorm -> fp32 + bf16 hi/lo ----------------------------
__global__ __launch_bounds__(256) void ln_kernel(
    const float* __restrict__ x, const float* __restrict__ g,
    const float* __restrict__ bb, float* __restrict__ o,
    __nv_bfloat16* __restrict__ oh, __nv_bfloat16* __restrict__ ol)
{
    int row = blockIdx.x, t = threadIdx.x;
    float v = x[(long)row * DIMC + t];
    int lane = t & 31, warp = t >> 5;
    __shared__ float sh[8];
    float s = v;
#pragma unroll
    for (int k = 16; k; k >>= 1) s += __shfl_xor_sync(0xffffffffu, s, k);
    if (lane == 0) sh[warp] = s;
    __syncthreads();
    float mean = (sh[0] + sh[1] + sh[2] + sh[3] + sh[4] + sh[5] + sh[6] + sh[7]) * (1.0f / 256.0f);
    float d = v - mean;
    float q = d * d;
#pragma unroll
    for (int k = 16; k; k >>= 1) q += __shfl_xor_sync(0xffffffffu, q, k);
    __syncthreads();
    if (lane == 0) sh[warp] = q;
    __syncthreads();
    float var = (sh[0] + sh[1] + sh[2] + sh[3] + sh[4] + sh[5] + sh[6] + sh[7]) * (1.0f / 256.0f);
    float rstd = rsqrtf(var + 1e-5f);
    float r = d * rstd * g[t] + bb[t];
    long idx = (long)row * DIMC + t;
    o[idx] = r;
    __nv_bfloat16 h, l;
    split_bf(r, h, l);
    oh[idx] = h; ol[idx] = l;
}

// ---------------- qk = relu(m_h @ W(32x64) + b); 8-wide register outputs ----
__global__ __launch_bounds__(256) void qk_kernel(
    const float* __restrict__ m, const float* __restrict__ W,
    const float* __restrict__ bias, float* __restrict__ q, float* __restrict__ kt)
{
    __shared__ float sm[16][DIMC];
    __shared__ float sw[32 * 64];
    __shared__ float sb[64];
    int t = threadIdx.x;
    int r0 = blockIdx.x * 16;
    for (int i = t; i < 16 * DIMC; i += 256)
        sm[i >> 8][i & 255] = m[(long)(r0 + (i >> 8)) * DIMC + (i & 255)];
    for (int i = t; i < 2048; i += 256) sw[i] = W[i];
    if (t < 64) sb[t] = bias[t];
    __syncthreads();
#pragma unroll
    for (int grp = 0; grp < 4; grp++) {
        int o8 = (grp * 256 + t) * 8;     // 0..8184 step 8
        int r = o8 >> 9;
        int rem = o8 & 511;
        int h = rem >> 6;
        int e0 = rem & 63;                // multiple of 8
        float acc[8];
#pragma unroll
        for (int j = 0; j < 8; j++) acc[j] = sb[e0 + j];
        const float* smr = &sm[r][h * 32];
#pragma unroll
        for (int c = 0; c < 32; c++) {
            float a = smr[c];
            float4 w0 = *(const float4*)&sw[c * 64 + e0];
            float4 w1 = *(const float4*)&sw[c * 64 + e0 + 4];
            acc[0] += a * w0.x; acc[1] += a * w0.y; acc[2] += a * w0.z; acc[3] += a * w0.w;
            acc[4] += a * w1.x; acc[5] += a * w1.y; acc[6] += a * w1.z; acc[7] += a * w1.w;
        }
        int row = r0 + r;
        int b = row >> 10, l = row & 1023;
        int bh = b * 8 + h;
        if (e0 < 32) {
            float* qp = &q[((long)bh * LSEQ + l) * 32 + e0];
#pragma unroll
            for (int j = 0; j < 8; j++) qp[j] = fmaxf(acc[j], 0.0f);
        } else {
#pragma unroll
            for (int j = 0; j < 8; j++)
                kt[((long)bh * 32 + (e0 - 32 + j)) * LSEQ + l] = fmaxf(acc[j], 0.0f);
        }
    }
}

// ======== phase-1 helper (32 q-rows): scores + softmax into S (smem) ========
#define A_FLOATS 9344
#define S_STRIDE 1028
__device__ __forceinline__ void score_softmax_phase32(
    const float* __restrict__ q, const float* __restrict__ kt,
    float* A, float* S, int bh, int r0, int t)
{
    float* Qs = A;
    float* Kg = A + 1024;
    {
        int r = t >> 3, k4 = (t & 7) * 4;
        float4 v = *(const float4*)(q + ((long)bh * LSEQ + r0 + r) * 32 + k4);
        Qs[(k4 + 0) * 32 + r] = v.x;
        Qs[(k4 + 1) * 32 + r] = v.y;
        Qs[(k4 + 2) * 32 + r] = v.z;
        Qs[(k4 + 3) * 32 + r] = v.w;
    }
    int tx = t & 63, ty = t >> 6;
    const float alpha = 1.0f / 32.0f;
    for (int g = 0; g < 4; g++) {
        __syncthreads();
        {
            int k = t >> 3;
            const float* src = kt + ((long)bh * 32 + k) * LSEQ + g * 256;
            float* dst = Kg + k * 260;
#pragma unroll
            for (int j = 0; j < 8; j++) {
                int c = ((t & 7) + 8 * j) * 4;
                *(float4*)(dst + c) = *(const float4*)(src + c);
            }
        }
        __syncthreads();
        float acc[8][4] = {};
#pragma unroll
        for (int k = 0; k < 32; k++) {
            float4 a0 = *(const float4*)&Qs[k * 32 + ty * 8];
            float4 a1 = *(const float4*)&Qs[k * 32 + ty * 8 + 4];
            float4 b  = *(const float4*)&Kg[k * 260 + (tx << 2)];
            float a[8] = {a0.x, a0.y, a0.z, a0.w, a1.x, a1.y, a1.z, a1.w};
#pragma unroll
            for (int i = 0; i < 8; i++) {
                acc[i][0] += a[i] * b.x;
                acc[i][1] += a[i] * b.y;
                acc[i][2] += a[i] * b.z;
                acc[i][3] += a[i] * b.w;
            }
        }
#pragma unroll
        for (int i = 0; i < 8; i++) {
            float4 v;
            v.x = acc[i][0] * alpha; v.y = acc[i][1] * alpha;
            v.z = acc[i][2] * alpha; v.w = acc[i][3] * alpha;
            *(float4*)&S[(ty * 8 + i) * S_STRIDE + g * 256 + (tx << 2)] = v;
        }
    }
    __syncthreads();
    int warp = t >> 5, lane = t & 31;
#pragma unroll
    for (int rr = 0; rr < 4; rr++) {
        int row = warp * 4 + rr;
        float* sp = S + row * S_STRIDE;
        float v[32];
        float mx = -INFINITY;
#pragma unroll
        for (int j = 0; j < 32; j++) { v[j] = sp[lane + 32 * j]; mx = fmaxf(mx, v[j]); }
#pragma unroll
        for (int o = 16; o; o >>= 1) mx = fmaxf(mx, __shfl_xor_sync(0xffffffffu, mx, o));
        float s = 0.0f;
#pragma unroll
        for (int j = 0; j < 32; j++) { v[j] = expf(v[j] - mx); s += v[j]; }
#pragma unroll
        for (int o = 16; o; o >>= 1) s += __shfl_xor_sync(0xffffffffu, s, o);
        float inv = 1.0f / s;
#pragma unroll
        for (int j = 0; j < 32; j++) sp[lane + 32 * j] = v[j] * inv;
    }
    __syncthreads();
}

// ---------------- layer-3: attention probs written to out -------------------
__global__ __launch_bounds__(256, 1) void attn_kernel(
    const float* __restrict__ q, const float* __restrict__ kt,
    float* __restrict__ out)
{
    extern __shared__ float smem[];
    float* A = smem;
    float* S = smem + A_FLOATS;
    int t = threadIdx.x;
    int bh = blockIdx.y;
    int r0 = blockIdx.x * 32;
    score_softmax_phase32(q, kt, A, S, bh, r0, t);
    float* op = out + ((long)bh * LSEQ + r0) * LSEQ;
#pragma unroll
    for (int j = 0; j < 32; j++) {
        int f = j * 256 + t;
        int row = f >> 8;
        int col = (f & 255) * 4;
        float4 v = *(const float4*)&S[row * S_STRIDE + col];
        *(float4*)(op + (long)row * LSEQ + col) = v;
    }
}

// ---------------- layers 0-2: fused score+softmax+PV+residual ---------------
__global__ __launch_bounds__(256, 1) void attn_mv_kernel(
    const float* __restrict__ q, const float* __restrict__ kt,
    const float* __restrict__ xn, float* __restrict__ mv_out)
{
    extern __shared__ float smem[];
    float* A = smem;
    float* S = smem + A_FLOATS;
    int t = threadIdx.x;
    int bh = blockIdx.y;
    int r0 = blockIdx.x * 32;
    int b = bh >> 3, h = bh & 7;
    score_softmax_phase32(q, kt, A, S, bh, r0, t);

    const float* xh = xn + (long)b * LSEQ * DIMC + h * 32;
    int g2 = t >> 5;
    int r2 = (t >> 3) & 3;
    int c2 = t & 7;
    float acc[8][4] = {};
    for (int chunk = 0; chunk < 4; chunk++) {
#pragma unroll
        for (int p = 0; p < 8; p++) {
            int row = (t >> 3) + 32 * p;
            int c4 = (t & 7) * 4;
            *(float4*)&A[row * 36 + c4] =
                *(const float4*)(xh + (long)(chunk * 256 + row) * DIMC + c4);
        }
        __syncthreads();
        int base = chunk * 256 + g2 * 32;
#pragma unroll
        for (int tt4 = 0; tt4 < 8; tt4++) {
            float4 xv0 = *(const float4*)&A[(g2 * 32 + tt4 * 4 + 0) * 36 + (c2 << 2)];
            float4 xv1 = *(const float4*)&A[(g2 * 32 + tt4 * 4 + 1) * 36 + (c2 << 2)];
            float4 xv2 = *(const float4*)&A[(g2 * 32 + tt4 * 4 + 2) * 36 + (c2 << 2)];
            float4 xv3 = *(const float4*)&A[(g2 * 32 + tt4 * 4 + 3) * 36 + (c2 << 2)];
#pragma unroll
            for (int i = 0; i < 8; i++) {
                float4 sv = *(const float4*)&S[(r2 * 8 + i) * S_STRIDE + base + tt4 * 4];
                acc[i][0] += sv.x * xv0.x + sv.y * xv1.x + sv.z * xv2.x + sv.w * xv3.x;
                acc[i][1] += sv.x * xv0.y + sv.y * xv1.y + sv.z * xv2.y + sv.w * xv3.y;
                acc[i][2] += sv.x * xv0.z + sv.y * xv1.z + sv.z * xv2.z + sv.w * xv3.z;
                acc[i][3] += sv.x * xv0.w + sv.y * xv1.w + sv.z * xv2.w + sv.w * xv3.w;
            }
        }
        __syncthreads();
    }
#pragma unroll
    for (int i = 0; i < 8; i++)
        *(float4*)&A[g2 * 1024 + (r2 * 8 + i) * 32 + (c2 << 2)] =
            make_float4(acc[i][0], acc[i][1], acc[i][2], acc[i][3]);
    __syncthreads();
#pragma unroll
    for (int rep = 0; rep < 4; rep++) {
        int o = t + 256 * rep;
        float val = 0.0f;
#pragma unroll
        for (int g = 0; g < 8; g++) val += A[g * 1024 + o];
        int row = o >> 5, col = o & 31;
        long gi = ((long)(b * LSEQ + r0 + row)) * DIMC + h * 32 + col;
        mv_out[gi] = val + xn[gi];
    }
}

// ---------------- v = gelu(relu(mv_h @ vW + vb)) -> bf16 hi/lo, 8-wide ------
__global__ __launch_bounds__(256) void v_kernel(
    const float* __restrict__ mv, const float* __restrict__ W,
    const float* __restrict__ bias,
    __nv_bfloat16* __restrict__ oh, __nv_bfloat16* __restrict__ ol)
{
    __shared__ float sm[16][DIMC];
    __shared__ float sw[32 * 32];
    __shared__ float sb[32];
    int t = threadIdx.x;
    int r0 = blockIdx.x * 16;
    for (int i = t; i < 16 * DIMC; i += 256)
        sm[i >> 8][i & 255] = mv[(long)(r0 + (i >> 8)) * DIMC + (i & 255)];
    for (int i = t; i < 1024; i += 256) sw[i] = W[i];
    if (t < 32) sb[t] = bias[t];
    __syncthreads();
#pragma unroll
    for (int grp = 0; grp < 2; grp++) {
        int o8 = (grp * 256 + t) * 8;     // over 16x256 outputs
        int r = o8 >> 8;
        int col0 = o8 & 255;              // multiple of 8
        int h = col0 >> 5;
        int d0 = col0 & 31;
        float acc[8];
#pragma unroll
        for (int j = 0; j < 8; j++) acc[j] = sb[d0 + j];
        const float* smr = &sm[r][h * 32];
#pragma unroll
        for (int c = 0; c < 32; c++) {
            float a = smr[c];
            float4 w0 = *(const float4*)&sw[c * 32 + d0];
            float4 w1 = *(const float4*)&sw[c * 32 + d0 + 4];
            acc[0] += a * w0.x; acc[1] += a * w0.y; acc[2] += a * w0.z; acc[3] += a * w0.w;
            acc[4] += a * w1.x; acc[5] += a * w1.y; acc[6] += a * w1.z; acc[7] += a * w1.w;
        }
        long idx = (long)(r0 + r) * DIMC + col0;
#pragma unroll
        for (int j = 0; j < 8; j++) {
            float gv = gelu_f(fmaxf(acc[j], 0.0f));
            __nv_bfloat16 hh, ll;
            split_bf(gv, hh, ll);
            oh[idx + j] = hh; ol[idx + j] = ll;
        }
    }
}

// ---------------- host orchestration ----------------------------------------
extern "C" void kernel_launch(void* const* d_in, const int* in_sizes, int n_in,
                              void* d_out, int out_size)
{
    (void)in_sizes; (void)n_in; (void)out_size;
    const float* img    = (const float*)d_in[0];
    const float* adj    = (const float*)d_in[1];
    const float* conv_w = (const float*)d_in[3];
    const float* conv_b = (const float*)d_in[4];
    const float* bn_g   = (const float*)d_in[5];
    const float* bn_b   = (const float*)d_in[6];
    const float* emb_w  = (const float*)d_in[7];
    const float* emb_b  = (const float*)d_in[8];
    const float* ln_g   = (const float*)d_in[9];
    const float* ln_b   = (const float*)d_in[10];
    const float* qk_w   = (const float*)d_in[11];
    const float* qk_b   = (const float*)d_in[12];
    const float* v_w    = (const float*)d_in[13];
    const float* v_b    = (const float*)d_in[14];
    const float* proj_w = (const float*)d_in[15];
    float* out = (float*)d_out;

    float *p_conv, *p_part, *p_stats, *p_x, *p_xn, *p_m, *p_q, *p_kt;
    __nv_bfloat16 *p_embin_h, *p_embin_l, *p_embw_h, *p_embw_l;
    __nv_bfloat16 *p_adj_h, *p_adj_l, *p_xn_h, *p_xn_l;
    __nv_bfloat16 *p_v_h, *p_v_l, *p_pw_h, *p_pw_l;
    cudaGetSymbolAddress((void**)&p_conv,  g_conv);
    cudaGetSymbolAddress((void**)&p_part,  g_part);
    cudaGetSymbolAddress((void**)&p_stats, g_stats);
    cudaGetSymbolAddress((void**)&p_x,     g_x);
    cudaGetSymbolAddress((void**)&p_xn,    g_xn);
    cudaGetSymbolAddress((void**)&p_m,     g_m);
    cudaGetSymbolAddress((void**)&p_q,     g_q);
    cudaGetSymbolAddress((void**)&p_kt,    g_kt);
    cudaGetSymbolAddress((void**)&p_embin_h, g_embin_h);
    cudaGetSymbolAddress((void**)&p_embin_l, g_embin_l);
    cudaGetSymbolAddress((void**)&p_embw_h,  g_embw_h);
    cudaGetSymbolAddress((void**)&p_embw_l,  g_embw_l);
    cudaGetSymbolAddress((void**)&p_adj_h,   g_adj_h);
    cudaGetSymbolAddress((void**)&p_adj_l,   g_adj_l);
    cudaGetSymbolAddress((void**)&p_xn_h,    g_xn_h);
    cudaGetSymbolAddress((void**)&p_xn_l,    g_xn_l);
    cudaGetSymbolAddress((void**)&p_v_h,     g_v_h);
    cudaGetSymbolAddress((void**)&p_v_l,     g_v_l);
    cudaGetSymbolAddress((void**)&p_pw_h,    g_pw_h);
    cudaGetSymbolAddress((void**)&p_pw_l,    g_pw_l);

    const int ATTN_SMEM = (A_FLOATS + 32 * S_STRIDE) * 4;   // 168,960 B
    static int smem_set = 0;
    if (!smem_set) {
        cudaFuncSetAttribute(attn_kernel,
                             cudaFuncAttributeMaxDynamicSharedMemorySize, ATTN_SMEM);
        cudaFuncSetAttribute(attn_mv_kernel,
                             cudaFuncAttributeMaxDynamicSharedMemorySize, ATTN_SMEM);
        smem_set = 1;
    }

    // one-time weight/adj splits
    split_kernel<<<(LSEQ * LSEQ + 255) / 256, 256>>>(adj, p_adj_h, p_adj_l, LSEQ * LSEQ);
    split_kernel<<<(PDIM * DIMC + 255) / 256, 256>>>(emb_w, p_embw_h, p_embw_l, PDIM * DIMC);
    split_kernel<<<(4 * DIMC * DIMC + 255) / 256, 256>>>(proj_w, p_pw_h, p_pw_l, 4 * DIMC * DIMC);

    conv_kernel<<<NPATCH, 256>>>(img, conv_w, conv_b, p_conv, p_part);
    bn_stats_kernel<<<ECH, 256>>>(p_part, p_stats);
    bn_gelu_pool_kernel<<<NPATCH, 256>>>(p_conv, p_stats, bn_g, bn_b,
                                         p_embin_h, p_embin_l);

    // embedding: (8192x1024) @ (1024x256) + bias
    gemm_bf<<<dim3(DIMC / 64, NPATCH / 128, 1), 256>>>(
        p_embin_h, p_embin_l, p_embw_h, p_embw_l, emb_b, nullptr, p_x, PDIM,
        0, 0, 0, PDIM, DIMC, 0, DIMC);

    const long LD = (long)LSEQ * DIMC;
    for (int i = 0; i < 4; i++) {
        ln_kernel<<<NPATCH, 256>>>(p_x, ln_g + i * DIMC, ln_b + i * DIMC,
                                   p_xn, p_xn_h, p_xn_l);
        // m = A @ xn + xn  per batch: M=1024, N=256, K=1024
        gemm_bf<<<dim3(DIMC / 64, LSEQ / 128, BATCH), 256>>>(
            p_adj_h, p_adj_l, p_xn_h, p_xn_l, nullptr, p_xn, p_m, LSEQ,
            LD, LD, LD, LSEQ, DIMC, DIMC, DIMC);
        qk_kernel<<<NPATCH / 16, 256>>>(p_m, qk_w + i * DHEAD * 2 * DHEAD,
                                        qk_b + i * 2 * DHEAD, p_q, p_kt);
        if (i < 3) {
            attn_mv_kernel<<<dim3(LSEQ / 32, BHDIM), 256, ATTN_SMEM>>>(
                p_q, p_kt, p_xn, p_m);
            v_kernel<<<NPATCH / 16, 256>>>(p_m, v_w + i * DHEAD * DHEAD,
                                           v_b + i * DHEAD, p_v_h, p_v_l);
            // x = v @ proj_w + xn : M=8192, N=256, K=256
            gemm_bf<<<dim3(DIMC / 64, NPATCH / 128, 1), 256>>>(
                p_v_h, p_v_l, p_pw_h + i * DIMC * DIMC, p_pw_l + i * DIMC * DIMC,
                nullptr, p_xn, p_x, DIMC,
                0, 0, 0, DIMC, DIMC, DIMC, DIMC);
        } else {
            attn_kernel<<<dim3(LSEQ / 32, BHDIM), 256, ATTN_SMEM>>>(p_q, p_kt, out);
        }
    }
}

// round 16
// speedup vs baseline: 1.1782x; 1.1782x over previous
#include <cuda_runtime.h>
#include <cuda_bf16.h>
#include <math.h>

#define BATCH 8
#define LSEQ 1024
#define DIMC 256
#define NHEADS 8
#define DHEAD 32
#define ECH 64
#define PDIM 1024
#define NPATCH 8192   // BATCH*LSEQ
#define BHDIM 64      // BATCH*NHEADS

// ---------------- scratch (device globals; no allocations allowed) ----------
__device__ float g_conv[NPATCH * ECH * 64];   // 128 MB
__device__ float g_part[NPATCH * 128];
__device__ float g_stats[ECH * 2];
__device__ float g_x[NPATCH * DIMC];
__device__ float g_xn[NPATCH * DIMC];
__device__ float g_m[NPATCH * DIMC];
__device__ float g_q[BHDIM * LSEQ * DHEAD];
__device__ float g_kt[BHDIM * DHEAD * LSEQ];

// bf16 hi/lo pre-split operands
__device__ __nv_bfloat16 g_embin_h[NPATCH * PDIM], g_embin_l[NPATCH * PDIM];
__device__ __nv_bfloat16 g_embw_h[PDIM * DIMC],   g_embw_l[PDIM * DIMC];
__device__ __nv_bfloat16 g_adj_h[LSEQ * LSEQ],    g_adj_l[LSEQ * LSEQ];
__device__ __nv_bfloat16 g_xn_h[NPATCH * DIMC],   g_xn_l[NPATCH * DIMC];
__device__ __nv_bfloat16 g_v_h[NPATCH * DIMC],    g_v_l[NPATCH * DIMC];
__device__ __nv_bfloat16 g_pw_h[4 * DIMC * DIMC], g_pw_l[4 * DIMC * DIMC];

__device__ __forceinline__ float gelu_f(float x) {
    return 0.5f * x * (1.0f + erff(x * 0.70710678118654752440f));
}

__device__ __forceinline__ void split_bf(float v, __nv_bfloat16& h, __nv_bfloat16& l) {
    h = __float2bfloat16(v);
    l = __float2bfloat16(v - __bfloat162float(h));
}

// ---------------- one-time fp32 -> bf16 hi/lo split -------------------------
__global__ __launch_bounds__(256) void split_kernel(
    const float* __restrict__ in, __nv_bfloat16* __restrict__ hi,
    __nv_bfloat16* __restrict__ lo, int n)
{
    int i = blockIdx.x * 256 + threadIdx.x;
    if (i < n) {
        __nv_bfloat16 h, l;
        split_bf(in[i], h, l);
        hi[i] = h; lo[i] = l;
    }
}

// ---------------- conv 3x3 s2 p1, register-tiled, low-smem ------------------
// thread: oc = t>>2, quadrant (qy,qx) of the 8x8 output; 27 weights in regs;
// BN partials reduced via 4-lane shuffle (no s_vals buffer): smem ~11 KB.
__global__ __launch_bounds__(256) void conv_kernel(
    const float* __restrict__ img, const float* __restrict__ w,
    const float* __restrict__ bias, float* __restrict__ out,
    float* __restrict__ part)
{
    int patch = blockIdx.x;
    int b  = patch >> 10;
    int gi = (patch >> 5) & 31;
    int gj = patch & 31;
    __shared__ float s_in[3][18][20];    // zero-padded border, 4320 B
    __shared__ float s_w[ECH * 27];      // 6912 B
    int t = threadIdx.x;
    for (int i = t; i < 3 * 18 * 20; i += 256) ((float*)s_in)[i] = 0.0f;
    for (int i = t; i < ECH * 27; i += 256) s_w[i] = w[i];
    __syncthreads();
    for (int i = t; i < 3 * 256; i += 256) {
        int c = i >> 8; int pi = (i >> 4) & 15; int pj = i & 15;
        s_in[c][pi + 1][pj + 1] =
            img[(((long)b * 3 + c) * 512 + gi * 16 + pi) * 512 + gj * 16 + pj];
    }
    __syncthreads();

    int oc = t >> 2, quad = t & 3;
    int qy = quad >> 1, qx = quad & 1;
    float wreg[27];
#pragma unroll
    for (int i = 0; i < 27; i++) wreg[i] = s_w[oc * 27 + i];
    float bv = bias[oc];
    float acc[4][4];
#pragma unroll
    for (int i = 0; i < 4; i++)
#pragma unroll
    for (int j = 0; j < 4; j++) acc[i][j] = bv;

#pragma unroll
    for (int c = 0; c < 3; c++) {
#pragma unroll
        for (int oy = 0; oy < 4; oy++) {
            int oyy = qy * 4 + oy;
            float rr[3][9];
#pragma unroll
            for (int ky = 0; ky < 3; ky++) {
                const float* rp = &s_in[c][2 * oyy + ky][8 * qx];
                float4 v0 = *(const float4*)rp;
                float4 v1 = *(const float4*)(rp + 4);
                rr[ky][0] = v0.x; rr[ky][1] = v0.y; rr[ky][2] = v0.z; rr[ky][3] = v0.w;
                rr[ky][4] = v1.x; rr[ky][5] = v1.y; rr[ky][6] = v1.z; rr[ky][7] = v1.w;
                rr[ky][8] = rp[8];
            }
            const float* wc = &wreg[c * 9];
#pragma unroll
            for (int ox = 0; ox < 4; ox++) {
                float a = acc[oy][ox];
#pragma unroll
                for (int ky = 0; ky < 3; ky++) {
                    a += rr[ky][2 * ox + 0] * wc[ky * 3 + 0];
                    a += rr[ky][2 * ox + 1] * wc[ky * 3 + 1];
                    a += rr[ky][2 * ox + 2] * wc[ky * 3 + 2];
                }
                acc[oy][ox] = a;
            }
        }
    }
    // float4 stores from registers + register BN partials
    float s = 0.0f, ss = 0.0f;
#pragma unroll
    for (int oy = 0; oy < 4; oy++) {
        int oyy = qy * 4 + oy;
        float4 v = make_float4(acc[oy][0], acc[oy][1], acc[oy][2], acc[oy][3]);
        *(float4*)&out[(long)patch * 4096 + oc * 64 + oyy * 8 + qx * 4] = v;
        s  += v.x + v.y + v.z + v.w;
        ss += v.x * v.x + v.y * v.y + v.z * v.z + v.w * v.w;
    }
    // combine the 4 lanes that share this oc (lanes t^1, t^2)
    s  += __shfl_xor_sync(0xffffffffu, s, 1);
    ss += __shfl_xor_sync(0xffffffffu, ss, 1);
    s  += __shfl_xor_sync(0xffffffffu, s, 2);
    ss += __shfl_xor_sync(0xffffffffu, ss, 2);
    if ((t & 3) == 0) {
        part[(long)patch * 128 + oc]      = s;
        part[(long)patch * 128 + 64 + oc] = ss;
    }
}

// ---------------- BN statistics from per-patch partials ---------------------
__global__ __launch_bounds__(256) void bn_stats_kernel(
    const float* __restrict__ part, float* __restrict__ stats)
{
    int c = blockIdx.x, t = threadIdx.x;
    double s = 0.0, ss = 0.0;
    for (int p = t; p < NPATCH; p += 256) {
        s  += (double)part[(long)p * 128 + c];
        ss += (double)part[(long)p * 128 + 64 + c];
    }
    __shared__ double sh1[256], sh2[256];
    sh1[t] = s; sh2[t] = ss;
    __syncthreads();
    for (int o = 128; o > 0; o >>= 1) {
        if (t < o) { sh1[t] += sh1[t + o]; sh2[t] += sh2[t + o]; }
        __syncthreads();
    }
    if (t == 0) {
        double mean = sh1[0] / 524288.0;
        double var  = sh2[0] / 524288.0 - mean * mean;
        stats[2 * c]     = (float)mean;
        stats[2 * c + 1] = rsqrtf((float)var + 1e-5f);
    }
}

// ---------------- BN + GELU + maxpool + flatten -> bf16 hi/lo ---------------
__global__ __launch_bounds__(256) void bn_gelu_pool_kernel(
    const float* __restrict__ conv, const float* __restrict__ stats,
    const float* __restrict__ bn_g, const float* __restrict__ bn_b,
    __nv_bfloat16* __restrict__ oh, __nv_bfloat16* __restrict__ ol)
{
    int patch = blockIdx.x;
    __shared__ float s[ECH * 64];
    int t = threadIdx.x;
    for (int i = t; i < ECH * 64; i += 256) {
        int c = i >> 6;
        float mean = stats[2 * c], rstd = stats[2 * c + 1];
        float x = (conv[(long)patch * 4096 + i] - mean) * rstd * bn_g[c] + bn_b[c];
        s[i] = gelu_f(x);
    }
    __syncthreads();
    for (int i = t; i < ECH * 16; i += 256) {
        int c = i >> 4; int pos = i & 15;
        int oy = pos >> 2, ox = pos & 3;
        float m = -INFINITY;
        for (int wy = 2 * oy - 1; wy <= 2 * oy + 1; wy++) {
            if (wy < 0 || wy > 7) continue;
            for (int wx = 2 * ox - 1; wx <= 2 * ox + 1; wx++) {
                if (wx < 0 || wx > 7) continue;
                m = fmaxf(m, s[c * 64 + wy * 8 + wx]);
            }
        }
        __nv_bfloat16 h, l;
        split_bf(m, h, l);
        oh[(long)patch * PDIM + i] = h;
        ol[(long)patch * PDIM + i] = l;
    }
}

// =====================================================================
// Pre-split 3xBF16 tensor-core GEMM: C = A@B (+bias)(+res), fp32 out.
// =====================================================================
__device__ __forceinline__ void mma_bf16(
    float& c0, float& c1, float& c2, float& c3,
    unsigned a0, unsigned a1, unsigned a2, unsigned a3,
    unsigned b0, unsigned b1)
{
    asm volatile(
        "mma.sync.aligned.m16n8k16.row.col.f32.bf16.bf16.f32 "
        "{%0,%1,%2,%3}, {%4,%5,%6,%7}, {%8,%9}, {%0,%1,%2,%3};"
        : "+f"(c0), "+f"(c1), "+f"(c2), "+f"(c3)
        : "r"(a0), "r"(a1), "r"(a2), "r"(a3), "r"(b0), "r"(b1));
}

__global__ __launch_bounds__(256, 2) void gemm_bf(
    const __nv_bfloat16* __restrict__ Ahg, const __nv_bfloat16* __restrict__ Alg,
    const __nv_bfloat16* __restrict__ Bhg, const __nv_bfloat16* __restrict__ Blg,
    const float* __restrict__ bias, const float* __restrict__ res,
    float* __restrict__ C, int K,
    long zB, long zRes, long zC,
    int lda, int ldb, int ldres, int ldc)
{
    long bz = blockIdx.z;
    Bhg += zB * bz; Blg += zB * bz; C += zC * bz;
    if (res) res += zRes * bz;
    int m0 = blockIdx.y * 128, n0 = blockIdx.x * 64;

    __shared__ __nv_bfloat16 Ash[128 * 40], Asl[128 * 40];
    __shared__ __nv_bfloat16 Bsh[64 * 40],  Bsl[64 * 40];

    int t = threadIdx.x, lane = t & 31, w = t >> 5;
    int wm = w & 3, wn = w >> 2;
    int gid = lane >> 2, tig = lane & 3;

    float acc[2][4][4] = {};

    int a_row[2], a_kq[2];
#pragma unroll
    for (int p = 0; p < 2; p++) {
        int i = t + 256 * p;
        a_row[p] = i >> 2;
        a_kq[p]  = (i & 3) * 8;
    }
    int b_kr = t >> 3, b_nq = (t & 7) * 8;

    uint4 arh[2], arl[2], brh, brl;
#pragma unroll
    for (int p = 0; p < 2; p++) {
        long off = (long)(m0 + a_row[p]) * lda + a_kq[p];
        arh[p] = *(const uint4*)(Ahg + off);
        arl[p] = *(const uint4*)(Alg + off);
    }
    {
        long off = (long)b_kr * ldb + n0 + b_nq;
        brh = *(const uint4*)(Bhg + off);
        brl = *(const uint4*)(Blg + off);
    }

    int nch = K >> 5;
    for (int c = 0; c < nch; c++) {
#pragma unroll
        for (int p = 0; p < 2; p++) {
            *(uint4*)&Ash[a_row[p] * 40 + a_kq[p]] = arh[p];
            *(uint4*)&Asl[a_row[p] * 40 + a_kq[p]] = arl[p];
        }
        {
            const __nv_bfloat16* h8 = (const __nv_bfloat16*)&brh;
            const __nv_bfloat16* l8 = (const __nv_bfloat16*)&brl;
#pragma unroll
            for (int j = 0; j < 8; j++) {
                Bsh[(b_nq + j) * 40 + b_kr] = h8[j];
                Bsl[(b_nq + j) * 40 + b_kr] = l8[j];
            }
        }
        __syncthreads();
        if (c + 1 < nch) {
            int kc = (c + 1) << 5;
#pragma unroll
            for (int p = 0; p < 2; p++) {
                long off = (long)(m0 + a_row[p]) * lda + kc + a_kq[p];
                arh[p] = *(const uint4*)(Ahg + off);
                arl[p] = *(const uint4*)(Alg + off);
            }
            long off = (long)(kc + b_kr) * ldb + n0 + b_nq;
            brh = *(const uint4*)(Bhg + off);
            brl = *(const uint4*)(Blg + off);
        }
#pragma unroll
        for (int ks = 0; ks < 2; ks++) {
            int k0 = ks * 16;
            unsigned bh[4][2], bl[4][2];
#pragma unroll
            for (int nt = 0; nt < 4; nt++) {
                int bb = (wn * 32 + nt * 8 + gid) * 40 + k0 + tig * 2;
                bh[nt][0] = *(const unsigned*)&Bsh[bb];
                bh[nt][1] = *(const unsigned*)&Bsh[bb + 8];
                bl[nt][0] = *(const unsigned*)&Bsl[bb];
                bl[nt][1] = *(const unsigned*)&Bsl[bb + 8];
            }
#pragma unroll
            for (int mt = 0; mt < 2; mt++) {
                int ab = (wm * 32 + mt * 16 + gid) * 40 + k0 + tig * 2;
                unsigned ah0 = *(const unsigned*)&Ash[ab];
                unsigned ah1 = *(const unsigned*)&Ash[ab + 8 * 40];
                unsigned ah2 = *(const unsigned*)&Ash[ab + 8];
                unsigned ah3 = *(const unsigned*)&Ash[ab + 8 * 40 + 8];
                unsigned al0 = *(const unsigned*)&Asl[ab];
                unsigned al1 = *(const unsigned*)&Asl[ab + 8 * 40];
                unsigned al2 = *(const unsigned*)&Asl[ab + 8];
                unsigned al3 = *(const unsigned*)&Asl[ab + 8 * 40 + 8];
#pragma unroll
                for (int nt = 0; nt < 4; nt++) {
                    float* cc = acc[mt][nt];
                    mma_bf16(cc[0], cc[1], cc[2], cc[3],
                             ah0, ah1, ah2, ah3, bh[nt][0], bh[nt][1]);
                    mma_bf16(cc[0], cc[1], cc[2], cc[3],
                             ah0, ah1, ah2, ah3, bl[nt][0], bl[nt][1]);
                    mma_bf16(cc[0], cc[1], cc[2], cc[3],
                             al0, al1, al2, al3, bh[nt][0], bh[nt][1]);
                }
            }
        }
        __syncthreads();
    }
#pragma unroll
    for (int mt = 0; mt < 2; mt++) {
        int r = m0 + wm * 32 + mt * 16 + gid;
#pragma unroll
        for (int nt = 0; nt < 4; nt++) {
            int n = n0 + wn * 32 + nt * 8 + tig * 2;
            float bx = 0.f, by = 0.f;
            if (bias) { float2 bv = *(const float2*)(bias + n); bx = bv.x; by = bv.y; }
            float* cc = acc[mt][nt];
            float2 v0 = make_float2(cc[0] + bx, cc[1] + by);
            float2 v1 = make_float2(cc[2] + bx, cc[3] + by);
            if (res) {
                float2 r0 = *(const float2*)(res + (long)r * ldres + n);
                float2 r1 = *(const float2*)(res + (long)(r + 8) * ldres + n);
                v0.x += r0.x; v0.y += r0.y; v1.x += r1.x; v1.y += r1.y;
            }
            *(float2*)(C + (long)r * ldc + n) = v0;
            *(float2*)(C + (long)(r + 8) * ldc + n) = v1;
        }
    }
}

// ---------------- layernorm -> fp32 + bf16 hi/lo ----------------------------
__global__ __launch_bounds__(256) void ln_kernel(
    const float* __restrict__ x, const float* __restrict__ g,
    const float* __restrict__ bb, float* __restrict__ o,
    __nv_bfloat16* __restrict__ oh, __nv_bfloat16* __restrict__ ol)
{
    int row = blockIdx.x, t = threadIdx.x;
    float v = x[(long)row * DIMC + t];
    int lane = t & 31, warp = t >> 5;
    __shared__ float sh[8];
    float s = v;
#pragma unroll
    for (int k = 16; k; k >>= 1) s += __shfl_xor_sync(0xffffffffu, s, k);
    if (lane == 0) sh[warp] = s;
    __syncthreads();
    float mean = (sh[0] + sh[1] + sh[2] + sh[3] + sh[4] + sh[5] + sh[6] + sh[7]) * (1.0f / 256.0f);
    float d = v - mean;
    float q = d * d;
#pragma unroll
    for (int k = 16; k; k >>= 1) q += __shfl_xor_sync(0xffffffffu, q, k);
    __syncthreads();
    if (lane == 0) sh[warp] = q;
    __syncthreads();
    float var = (sh[0] + sh[1] + sh[2] + sh[3] + sh[4] + sh[5] + sh[6] + sh[7]) * (1.0f / 256.0f);
    float rstd = rsqrtf(var + 1e-5f);
    float r = d * rstd * g[t] + bb[t];
    long idx = (long)row * DIMC + t;
    o[idx] = r;
    __nv_bfloat16 h, l;
    split_bf(r, h, l);
    oh[idx] = h; ol[idx] = l;
}

// ---------------- qk = relu(m_h @ W(32x64) + b); q row-major, k transposed --
__global__ __launch_bounds__(256) void qk_kernel(
    const float* __restrict__ m, const float* __restrict__ W,
    const float* __restrict__ bias, float* __restrict__ q, float* __restrict__ kt)
{
    __shared__ float sm[16][DIMC];
    __shared__ float sw[32 * 64];
    __shared__ float sb[64];
    int t = threadIdx.x;
    int r0 = blockIdx.x * 16;
    for (int i = t; i < 16 * DIMC; i += 256)
        sm[i >> 8][i & 255] = m[(long)(r0 + (i >> 8)) * DIMC + (i & 255)];
    for (int i = t; i < 2048; i += 256) sw[i] = W[i];
    if (t < 64) sb[t] = bias[t];
    __syncthreads();
    for (int o = t; o < 8192; o += 256) {
        int r = o >> 9;
        int rem = o & 511;
        int h = rem >> 6;
        int e = rem & 63;
        float acc = sb[e];
#pragma unroll
        for (int c = 0; c < 32; c++) acc += sm[r][h * 32 + c] * sw[c * 64 + e];
        acc = fmaxf(acc, 0.0f);
        int row = r0 + r;
        int b = row >> 10, l = row & 1023;
        int bh = b * 8 + h;
        if (e < 32) q[((long)bh * LSEQ + l) * 32 + e] = acc;
        else        kt[((long)bh * 32 + (e - 32)) * LSEQ + l] = acc;
    }
}

// ======== phase-1 helper (32 q-rows): scores + softmax into S (smem) ========
#define A_FLOATS 9344
#define S_STRIDE 1028
__device__ __forceinline__ void score_softmax_phase32(
    const float* __restrict__ q, const float* __restrict__ kt,
    float* A, float* S, int bh, int r0, int t)
{
    float* Qs = A;
    float* Kg = A + 1024;
    {
        int r = t >> 3, k4 = (t & 7) * 4;
        float4 v = *(const float4*)(q + ((long)bh * LSEQ + r0 + r) * 32 + k4);
        Qs[(k4 + 0) * 32 + r] = v.x;
        Qs[(k4 + 1) * 32 + r] = v.y;
        Qs[(k4 + 2) * 32 + r] = v.z;
        Qs[(k4 + 3) * 32 + r] = v.w;
    }
    int tx = t & 63, ty = t >> 6;
    const float alpha = 1.0f / 32.0f;
    for (int g = 0; g < 4; g++) {
        __syncthreads();
        {
            int k = t >> 3;
            const float* src = kt + ((long)bh * 32 + k) * LSEQ + g * 256;
            float* dst = Kg + k * 260;
#pragma unroll
            for (int j = 0; j < 8; j++) {
                int c = ((t & 7) + 8 * j) * 4;
                *(float4*)(dst + c) = *(const float4*)(src + c);
            }
        }
        __syncthreads();
        float acc[8][4] = {};
#pragma unroll
        for (int k = 0; k < 32; k++) {
            float4 a0 = *(const float4*)&Qs[k * 32 + ty * 8];
            float4 a1 = *(const float4*)&Qs[k * 32 + ty * 8 + 4];
            float4 b  = *(const float4*)&Kg[k * 260 + (tx << 2)];
            float a[8] = {a0.x, a0.y, a0.z, a0.w, a1.x, a1.y, a1.z, a1.w};
#pragma unroll
            for (int i = 0; i < 8; i++) {
                acc[i][0] += a[i] * b.x;
                acc[i][1] += a[i] * b.y;
                acc[i][2] += a[i] * b.z;
                acc[i][3] += a[i] * b.w;
            }
        }
#pragma unroll
        for (int i = 0; i < 8; i++) {
            float4 v;
            v.x = acc[i][0] * alpha; v.y = acc[i][1] * alpha;
            v.z = acc[i][2] * alpha; v.w = acc[i][3] * alpha;
            *(float4*)&S[(ty * 8 + i) * S_STRIDE + g * 256 + (tx << 2)] = v;
        }
    }
    __syncthreads();
    int warp = t >> 5, lane = t & 31;
#pragma unroll
    for (int rr = 0; rr < 4; rr++) {
        int row = warp * 4 + rr;
        float* sp = S + row * S_STRIDE;
        float v[32];
        float mx = -INFINITY;
#pragma unroll
        for (int j = 0; j < 32; j++) { v[j] = sp[lane + 32 * j]; mx = fmaxf(mx, v[j]); }
#pragma unroll
        for (int o = 16; o; o >>= 1) mx = fmaxf(mx, __shfl_xor_sync(0xffffffffu, mx, o));
        float s = 0.0f;
#pragma unroll
        for (int j = 0; j < 32; j++) { v[j] = expf(v[j] - mx); s += v[j]; }
#pragma unroll
        for (int o = 16; o; o >>= 1) s += __shfl_xor_sync(0xffffffffu, s, o);
        float inv = 1.0f / s;
#pragma unroll
        for (int j = 0; j < 32; j++) sp[lane + 32 * j] = v[j] * inv;
    }
    __syncthreads();
}

// ---------------- layer-3: attention probs written to out -------------------
__global__ __launch_bounds__(256, 1) void attn_kernel(
    const float* __restrict__ q, const float* __restrict__ kt,
    float* __restrict__ out)
{
    extern __shared__ float smem[];
    float* A = smem;
    float* S = smem + A_FLOATS;
    int t = threadIdx.x;
    int bh = blockIdx.y;
    int r0 = blockIdx.x * 32;
    score_softmax_phase32(q, kt, A, S, bh, r0, t);
    float* op = out + ((long)bh * LSEQ + r0) * LSEQ;
#pragma unroll
    for (int j = 0; j < 32; j++) {
        int f = j * 256 + t;
        int row = f >> 8;
        int col = (f & 255) * 4;
        float4 v = *(const float4*)&S[row * S_STRIDE + col];
        *(float4*)(op + (long)row * LSEQ + col) = v;
    }
}

// ---------------- layers 0-2: fused score+softmax+PV+residual ---------------
__global__ __launch_bounds__(256, 1) void attn_mv_kernel(
    const float* __restrict__ q, const float* __restrict__ kt,
    const float* __restrict__ xn, float* __restrict__ mv_out)
{
    extern __shared__ float smem[];
    float* A = smem;
    float* S = smem + A_FLOATS;
    int t = threadIdx.x;
    int bh = blockIdx.y;
    int r0 = blockIdx.x * 32;
    int b = bh >> 3, h = bh & 7;
    score_softmax_phase32(q, kt, A, S, bh, r0, t);

    const float* xh = xn + (long)b * LSEQ * DIMC + h * 32;
    int g2 = t >> 5;
    int r2 = (t >> 3) & 3;
    int c2 = t & 7;
    float acc[8][4] = {};
    for (int chunk = 0; chunk < 4; chunk++) {
#pragma unroll
        for (int p = 0; p < 8; p++) {
            int row = (t >> 3) + 32 * p;
            int c4 = (t & 7) * 4;
            *(float4*)&A[row * 36 + c4] =
                *(const float4*)(xh + (long)(chunk * 256 + row) * DIMC + c4);
        }
        __syncthreads();
        int base = chunk * 256 + g2 * 32;
#pragma unroll
        for (int tt4 = 0; tt4 < 8; tt4++) {
            float4 xv0 = *(const float4*)&A[(g2 * 32 + tt4 * 4 + 0) * 36 + (c2 << 2)];
            float4 xv1 = *(const float4*)&A[(g2 * 32 + tt4 * 4 + 1) * 36 + (c2 << 2)];
            float4 xv2 = *(const float4*)&A[(g2 * 32 + tt4 * 4 + 2) * 36 + (c2 << 2)];
            float4 xv3 = *(const float4*)&A[(g2 * 32 + tt4 * 4 + 3) * 36 + (c2 << 2)];
#pragma unroll
            for (int i = 0; i < 8; i++) {
                float4 sv = *(const float4*)&S[(r2 * 8 + i) * S_STRIDE + base + tt4 * 4];
                acc[i][0] += sv.x * xv0.x + sv.y * xv1.x + sv.z * xv2.x + sv.w * xv3.x;
                acc[i][1] += sv.x * xv0.y + sv.y * xv1.y + sv.z * xv2.y + sv.w * xv3.y;
                acc[i][2] += sv.x * xv0.z + sv.y * xv1.z + sv.z * xv2.z + sv.w * xv3.z;
                acc[i][3] += sv.x * xv0.w + sv.y * xv1.w + sv.z * xv2.w + sv.w * xv3.w;
            }
        }
        __syncthreads();
    }
#pragma unroll
    for (int i = 0; i < 8; i++)
        *(float4*)&A[g2 * 1024 + (r2 * 8 + i) * 32 + (c2 << 2)] =
            make_float4(acc[i][0], acc[i][1], acc[i][2], acc[i][3]);
    __syncthreads();
#pragma unroll
    for (int rep = 0; rep < 4; rep++) {
        int o = t + 256 * rep;
        float val = 0.0f;
#pragma unroll
        for (int g = 0; g < 8; g++) val += A[g * 1024 + o];
        int row = o >> 5, col = o & 31;
        long gi = ((long)(b * LSEQ + r0 + row)) * DIMC + h * 32 + col;
        mv_out[gi] = val + xn[gi];
    }
}

// ---------------- v = gelu(relu(mv_h @ vW(32x32) + vb)) -> bf16 hi/lo -------
__global__ __launch_bounds__(256) void v_kernel(
    const float* __restrict__ mv, const float* __restrict__ W,
    const float* __restrict__ bias,
    __nv_bfloat16* __restrict__ oh, __nv_bfloat16* __restrict__ ol)
{
    __shared__ float sm[16][DIMC];
    __shared__ float sw[32 * 32];
    __shared__ float sb[32];
    int t = threadIdx.x;
    int r0 = blockIdx.x * 16;
    for (int i = t; i < 16 * DIMC; i += 256)
        sm[i >> 8][i & 255] = mv[(long)(r0 + (i >> 8)) * DIMC + (i & 255)];
    for (int i = t; i < 1024; i += 256) sw[i] = W[i];
    if (t < 32) sb[t] = bias[t];
    __syncthreads();
    for (int o = t; o < 4096; o += 256) {
        int r = o >> 8, col = o & 255;
        int h = col >> 5, d = col & 31;
        float acc = sb[d];
#pragma unroll
        for (int c = 0; c < 32; c++) acc += sm[r][h * 32 + c] * sw[c * 32 + d];
        acc = fmaxf(acc, 0.0f);
        float gv = gelu_f(acc);
        __nv_bfloat16 hh, ll;
        split_bf(gv, hh, ll);
        long idx = (long)(r0 + r) * DIMC + col;
        oh[idx] = hh; ol[idx] = ll;
    }
}

// ---------------- host orchestration ----------------------------------------
extern "C" void kernel_launch(void* const* d_in, const int* in_sizes, int n_in,
                              void* d_out, int out_size)
{
    (void)in_sizes; (void)n_in; (void)out_size;
    const float* img    = (const float*)d_in[0];
    const float* adj    = (const float*)d_in[1];
    const float* conv_w = (const float*)d_in[3];
    const float* conv_b = (const float*)d_in[4];
    const float* bn_g   = (const float*)d_in[5];
    const float* bn_b   = (const float*)d_in[6];
    const float* emb_w  = (const float*)d_in[7];
    const float* emb_b  = (const float*)d_in[8];
    const float* ln_g   = (const float*)d_in[9];
    const float* ln_b   = (const float*)d_in[10];
    const float* qk_w   = (const float*)d_in[11];
    const float* qk_b   = (const float*)d_in[12];
    const float* v_w    = (const float*)d_in[13];
    const float* v_b    = (const float*)d_in[14];
    const float* proj_w = (const float*)d_in[15];
    float* out = (float*)d_out;

    float *p_conv, *p_part, *p_stats, *p_x, *p_xn, *p_m, *p_q, *p_kt;
    __nv_bfloat16 *p_embin_h, *p_embin_l, *p_embw_h, *p_embw_l;
    __nv_bfloat16 *p_adj_h, *p_adj_l, *p_xn_h, *p_xn_l;
    __nv_bfloat16 *p_v_h, *p_v_l, *p_pw_h, *p_pw_l;
    cudaGetSymbolAddress((void**)&p_conv,  g_conv);
    cudaGetSymbolAddress((void**)&p_part,  g_part);
    cudaGetSymbolAddress((void**)&p_stats, g_stats);
    cudaGetSymbolAddress((void**)&p_x,     g_x);
    cudaGetSymbolAddress((void**)&p_xn,    g_xn);
    cudaGetSymbolAddress((void**)&p_m,     g_m);
    cudaGetSymbolAddress((void**)&p_q,     g_q);
    cudaGetSymbolAddress((void**)&p_kt,    g_kt);
    cudaGetSymbolAddress((void**)&p_embin_h, g_embin_h);
    cudaGetSymbolAddress((void**)&p_embin_l, g_embin_l);
    cudaGetSymbolAddress((void**)&p_embw_h,  g_embw_h);
    cudaGetSymbolAddress((void**)&p_embw_l,  g_embw_l);
    cudaGetSymbolAddress((void**)&p_adj_h,   g_adj_h);
    cudaGetSymbolAddress((void**)&p_adj_l,   g_adj_l);
    cudaGetSymbolAddress((void**)&p_xn_h,    g_xn_h);
    cudaGetSymbolAddress((void**)&p_xn_l,    g_xn_l);
    cudaGetSymbolAddress((void**)&p_v_h,     g_v_h);
    cudaGetSymbolAddress((void**)&p_v_l,     g_v_l);
    cudaGetSymbolAddress((void**)&p_pw_h,    g_pw_h);
    cudaGetSymbolAddress((void**)&p_pw_l,    g_pw_l);

    const int ATTN_SMEM = (A_FLOATS + 32 * S_STRIDE) * 4;   // 168,960 B
    static int smem_set = 0;
    if (!smem_set) {
        cudaFuncSetAttribute(attn_kernel,
                             cudaFuncAttributeMaxDynamicSharedMemorySize, ATTN_SMEM);
        cudaFuncSetAttribute(attn_mv_kernel,
                             cudaFuncAttributeMaxDynamicSharedMemorySize, ATTN_SMEM);
        smem_set = 1;
    }

    // one-time weight/adj splits
    split_kernel<<<(LSEQ * LSEQ + 255) / 256, 256>>>(adj, p_adj_h, p_adj_l, LSEQ * LSEQ);
    split_kernel<<<(PDIM * DIMC + 255) / 256, 256>>>(emb_w, p_embw_h, p_embw_l, PDIM * DIMC);
    split_kernel<<<(4 * DIMC * DIMC + 255) / 256, 256>>>(proj_w, p_pw_h, p_pw_l, 4 * DIMC * DIMC);

    conv_kernel<<<NPATCH, 256>>>(img, conv_w, conv_b, p_conv, p_part);
    bn_stats_kernel<<<ECH, 256>>>(p_part, p_stats);
    bn_gelu_pool_kernel<<<NPATCH, 256>>>(p_conv, p_stats, bn_g, bn_b,
                                         p_embin_h, p_embin_l);

    // embedding: (8192x1024) @ (1024x256) + bias
    gemm_bf<<<dim3(DIMC / 64, NPATCH / 128, 1), 256>>>(
        p_embin_h, p_embin_l, p_embw_h, p_embw_l, emb_b, nullptr, p_x, PDIM,
        0, 0, 0, PDIM, DIMC, 0, DIMC);

    const long LD = (long)LSEQ * DIMC;
    for (int i = 0; i < 4; i++) {
        ln_kernel<<<NPATCH, 256>>>(p_x, ln_g + i * DIMC, ln_b + i * DIMC,
                                   p_xn, p_xn_h, p_xn_l);
        // m = A @ xn + xn  per batch: M=1024, N=256, K=1024
        gemm_bf<<<dim3(DIMC / 64, LSEQ / 128, BATCH), 256>>>(
            p_adj_h, p_adj_l, p_xn_h, p_xn_l, nullptr, p_xn, p_m, LSEQ,
            LD, LD, LD, LSEQ, DIMC, DIMC, DIMC);
        qk_kernel<<<NPATCH / 16, 256>>>(p_m, qk_w + i * DHEAD * 2 * DHEAD,
                                        qk_b + i * 2 * DHEAD, p_q, p_kt);
        if (i < 3) {
            attn_mv_kernel<<<dim3(LSEQ / 32, BHDIM), 256, ATTN_SMEM>>>(
                p_q, p_kt, p_xn, p_m);
            v_kernel<<<NPATCH / 16, 256>>>(p_m, v_w + i * DHEAD * DHEAD,
                                           v_b + i * DHEAD, p_v_h, p_v_l);
            // x = v @ proj_w + xn : M=8192, N=256, K=256
            gemm_bf<<<dim3(DIMC / 64, NPATCH / 128, 1), 256>>>(
                p_v_h, p_v_l, p_pw_h + i * DIMC * DIMC, p_pw_l + i * DIMC * DIMC,
                nullptr, p_xn, p_x, DIMC,
                0, 0, 0, DIMC, DIMC, DIMC, DIMC);
        } else {
            attn_kernel<<<dim3(LSEQ / 32, BHDIM), 256, ATTN_SMEM>>>(p_q, p_kt, out);
        }
    }
}